// round 1
// baseline (speedup 1.0000x reference)
#include <cuda_runtime.h>
#include <math.h>

// Problem constants
#define B_  16
#define C_  128
#define O_  256
#define H_  96
#define W_  96
#define KH  5
#define HO  92
#define WO  92
#define HW_IN  (H_*W_)        // 9216
#define HW_OUT (HO*WO)        // 8464
#define KK  (KH*KH)           // 25
#define CK  (C_*KK)           // 3200

// Scratch (device globals — no allocations allowed)
__device__ float g_Wt [C_*KK*O_];   // [c][k][o]   W transposed
__device__ float g_Wt2[C_*KK*O_];   // [c][k][o]   W^2 transposed
__device__ float g_T  [B_*HW_IN];   // per-pixel channel sum of (sigma + mu^2)
__device__ float g_S  [B_*HW_OUT];  // 5x5 box filter of g_T
__device__ float g_sp [O_];         // softplus(w_sigma)

// ---------------------------------------------------------------------------
// Prep: transpose weights to [c*25+k][o], square them, compute softplus.
// ---------------------------------------------------------------------------
__global__ void prep_kernel(const float* __restrict__ W,
                            const float* __restrict__ w_sigma) {
    int i = blockIdx.x * blockDim.x + threadIdx.x;
    if (i < O_) {
        float w = fmaxf(w_sigma[i], -88.0f);
        g_sp[i] = log1pf(expf(w));
    }
    if (i < O_*CK) {
        int o = i / CK;          // output channel
        int r = i - o * CK;      // c*25+k
        float w = W[i];          // coalesced read (W is [o][c][kh][kw])
        int dst = r * O_ + o;
        g_Wt [dst] = w;
        g_Wt2[dst] = w * w;
    }
}

// ---------------------------------------------------------------------------
// T[b,y,x] = sum_c ( sigma_x[b,c,y,x] + mu_x[b,c,y,x]^2 )
// ---------------------------------------------------------------------------
__global__ void chansum_kernel(const float* __restrict__ mu,
                               const float* __restrict__ sg) {
    int i = blockIdx.x * blockDim.x + threadIdx.x;
    if (i >= B_*HW_IN) return;
    int b = i / HW_IN;
    int p = i - b * HW_IN;
    const float* m = mu + (size_t)b * C_ * HW_IN + p;
    const float* s = sg + (size_t)b * C_ * HW_IN + p;
    float acc = 0.0f;
    #pragma unroll 8
    for (int c = 0; c < C_; ++c) {
        float mv = m[c * HW_IN];
        acc += s[c * HW_IN] + mv * mv;
    }
    g_T[i] = acc;
}

// ---------------------------------------------------------------------------
// S[b,y,x] = 5x5 box sum of T (VALID)
// ---------------------------------------------------------------------------
__global__ void boxsum_kernel() {
    int i = blockIdx.x * blockDim.x + threadIdx.x;
    if (i >= B_*HW_OUT) return;
    int b = i / HW_OUT;
    int p = i - b * HW_OUT;
    int y = p / WO;
    int x = p - y * WO;
    const float* t = g_T + b * HW_IN;
    float acc = 0.0f;
    #pragma unroll
    for (int dy = 0; dy < KH; ++dy)
        #pragma unroll
        for (int dx = 0; dx < KH; ++dx)
            acc += t[(y + dy) * W_ + (x + dx)];
    g_S[i] = acc;
}

// ---------------------------------------------------------------------------
// Main conv: implicit GEMM. Block tile = 128 o x (8 rows x 16 cols) pixels.
// 256 threads, thread tile 8o x 8px (one row, 8 consecutive cols).
// blockIdx.z encodes (b, og, path):  path 0 = mu conv(W), path 1 = sigma conv(W^2)
// ---------------------------------------------------------------------------
#define TROWS 8
#define TCOLS 16
#define INROWS (TROWS + KH - 1)   // 12
#define INCOLS (TCOLS + KH - 1)   // 20
#define INPITCH 21                // conflict-free pad

__global__ __launch_bounds__(256, 2)
void conv_kernel(const float* __restrict__ mu_x,
                 const float* __restrict__ sg_x,
                 const float* __restrict__ bias,
                 float* __restrict__ out) {
    int z    = blockIdx.z;
    int path = z & 1;
    int og   = (z >> 1) & 1;
    int b    = z >> 2;

    const float* x  = path ? sg_x  : mu_x;
    const float* wt = path ? g_Wt2 : g_Wt;

    int x0 = blockIdx.x * TCOLS;
    int y0 = blockIdx.y * TROWS;

    __shared__ float Wsm[KK * 128];          // [k][o_local 0..127]
    __shared__ float In [INROWS * INPITCH];  // padded input patch

    int tid  = threadIdx.x;
    int to   = tid >> 4;          // 0..15 -> 8 o's each
    int tp   = tid & 15;          // 0..15 pixel group
    int prow = tp >> 1;           // 0..7
    int pcb  = (tp & 1) * 8;      // 0 or 8

    float acc[8][8];
    #pragma unroll
    for (int a = 0; a < 8; ++a)
        #pragma unroll
        for (int j = 0; j < 8; ++j) acc[a][j] = 0.0f;

    const float* wbase = wt + og * 128;

    for (int c = 0; c < C_; ++c) {
        // --- stage weights: 25 x 128 floats, coalesced ---
        const float* wsrc = wbase + (size_t)c * KK * O_;
        #pragma unroll
        for (int i = tid; i < KK * 128; i += 256) {
            int k = i >> 7;
            int j = i & 127;
            Wsm[i] = wsrc[k * O_ + j];
        }
        // --- stage input patch 12x20 (zero-padded OOB) ---
        const float* xsrc = x + ((size_t)(b * C_ + c)) * HW_IN;
        if (tid < INROWS * INPITCH) {
            int r  = tid / INPITCH;
            int cc = tid - r * INPITCH;
            float v = 0.0f;
            int gy = y0 + r, gx = x0 + cc;
            if (cc < INCOLS && gy < H_ && gx < W_) v = xsrc[gy * W_ + gx];
            In[tid] = v;
        }
        __syncthreads();

        #pragma unroll
        for (int ki = 0; ki < KH; ++ki) {
            #pragma unroll
            for (int kj = 0; kj < KH; ++kj) {
                int k = ki * KH + kj;
                float wv[8];
                *(float4*)&wv[0] = *(const float4*)&Wsm[k * 128 + to * 8];
                *(float4*)&wv[4] = *(const float4*)&Wsm[k * 128 + to * 8 + 4];
                float iv[8];
                int base = (prow + ki) * INPITCH + pcb + kj;
                #pragma unroll
                for (int j = 0; j < 8; ++j) iv[j] = In[base + j];
                #pragma unroll
                for (int a = 0; a < 8; ++a)
                    #pragma unroll
                    for (int j = 0; j < 8; ++j)
                        acc[a][j] = fmaf(wv[a], iv[j], acc[a][j]);
            }
        }
        __syncthreads();
    }

    // --- epilogue ---
    int y = y0 + prow;
    if (y >= HO) return;

    if (path == 0) {
        #pragma unroll
        for (int a = 0; a < 8; ++a) {
            int o = og * 128 + to * 8 + a;
            float bz = bias[o];
            float* op = out + ((size_t)(b * O_ + o) * HO + y) * WO;
            #pragma unroll
            for (int j = 0; j < 8; ++j) {
                int xx = x0 + pcb + j;
                if (xx < WO) op[xx] = acc[a][j] + bz;
            }
        }
    } else {
        float* out2 = out + (size_t)B_ * O_ * HW_OUT;
        float sv[8];
        const float* srow = g_S + (b * HO + y) * WO;
        #pragma unroll
        for (int j = 0; j < 8; ++j) {
            int xx = x0 + pcb + j;
            sv[j] = (xx < WO) ? srow[xx] : 0.0f;
        }
        #pragma unroll
        for (int a = 0; a < 8; ++a) {
            int o = og * 128 + to * 8 + a;
            float spo = g_sp[o];
            float* op = out2 + ((size_t)(b * O_ + o) * HO + y) * WO;
            #pragma unroll
            for (int j = 0; j < 8; ++j) {
                int xx = x0 + pcb + j;
                if (xx < WO) op[xx] = (spo * sv[j] + acc[a][j]) * 0.001f;
            }
        }
    }
}

// ---------------------------------------------------------------------------
extern "C" void kernel_launch(void* const* d_in, const int* in_sizes, int n_in,
                              void* d_out, int out_size) {
    const float* mu_x    = (const float*)d_in[0];
    const float* sigma_x = (const float*)d_in[1];
    const float* W       = (const float*)d_in[2];
    const float* bias    = (const float*)d_in[3];
    const float* w_sigma = (const float*)d_in[4];
    float* out = (float*)d_out;

    {
        int n = O_ * CK;
        prep_kernel<<<(n + 255) / 256, 256>>>(W, w_sigma);
    }
    {
        int n = B_ * HW_IN;
        chansum_kernel<<<(n + 255) / 256, 256>>>(mu_x, sigma_x);
    }
    {
        int n = B_ * HW_OUT;
        boxsum_kernel<<<(n + 255) / 256, 256>>>();
    }
    {
        dim3 grid((WO + TCOLS - 1) / TCOLS,   // 6
                  (HO + TROWS - 1) / TROWS,   // 12
                  B_ * 2 * 2);                // b * og * path = 64
        conv_kernel<<<grid, 256>>>(mu_x, sigma_x, bias, out);
    }
}